// round 1
// baseline (speedup 1.0000x reference)
#include <cuda_runtime.h>
#include <math.h>

#define NB 16
#define NT 60
#define NCLS 80

__constant__ float cANW[9] = {12.f,19.f,40.f,36.f,76.f,72.f,142.f,192.f,459.f};
__constant__ float cANH[9] = {16.f,36.f,28.f,75.f,55.f,146.f,110.f,243.f,401.f};

#define NC0 (3*76*76)      /* 17328 cells per (b) at level 0 */
#define NC1 (3*38*38)      /* 4332  */
#define NC2 (3*19*19)      /* 1083  */
#define CMOFF1 (NB*NC0)            /* 277248 */
#define CMOFF2 (CMOFF1+NB*NC1)     /* 346560 */
#define NCM    (CMOFF2+NB*NC2)     /* 363888 */

#define CH0 68   /* ceil(NC0/256) */
#define CH1 17   /* ceil(NC1/256) */
#define CH2 5    /* ceil(NC2/256) */
#define GB0 (NB*CH0)          /* 1088 */
#define GB1 (GB0+NB*CH1)      /* 1360 */
#define GB2 (GB1+NB*CH2)      /* 1440 */

__device__ float4 g_tbox[3][NB][NT];
__device__ float  g_tarea[3][NB][NT];
__device__ int    g_minfo[3][NB][NT];
__device__ int    g_hm[3][NB];
__device__ int    g_cm[NCM];

__device__ __forceinline__ float clogf_(float v){ return fmaxf(logf(v), -100.0f); }
__device__ __forceinline__ float sigf_(float v){ return 1.0f/(1.0f+expf(-v)); }

// ---------------------------------------------------------------- clear
__global__ void k_clear(float* __restrict__ gout){
  int i = blockIdx.x*blockDim.x + threadIdx.x;
  if (i < NCM) g_cm[i] = -1;
  if (i < 6)  gout[i] = 0.0f;
}

// ---------------------------------------------------------------- prep1: per-(b,t) truth boxes + ciou argmax
__global__ void k_prep1(const float* __restrict__ labels){
  int idx = blockIdx.x*blockDim.x + threadIdx.x;
  if (idx >= NB*NT) return;
  int b = idx / NT, t = idx - b*NT;
  const float* lp = labels + idx*5;
  float a0 = lp[0], a1 = lp[1], a2 = lp[2], a3 = lp[3], a4 = lp[4];
  bool valid = (a0+a1+a2+a3+a4) > 0.0f;
  const float invsArr[3] = {0.125f, 0.0625f, 0.03125f};
  const int   fsArr[3]   = {76, 38, 19};
  #pragma unroll
  for (int L = 0; L < 3; L++){
    float invs = invsArr[L];
    int   fs   = fsArr[L];
    float tx = (a2+a0)*(0.5f*invs);            // exact: stride*2 is a power of two
    float ty = (a3+a1)*(0.5f*invs);
    float tw = (a2-a0)*invs;
    float th = (a3-a1)*invs;
    float4 tb; float ar;
    if (valid){
      tb = make_float4(tx - tw*0.5f, ty - th*0.5f, tx + tw*0.5f, ty + th*0.5f);
      ar = tw*th;
    } else { tb = make_float4(0.f,0.f,0.f,0.f); ar = 0.f; }
    g_tbox[L][b][t]  = tb;
    g_tarea[L][b][t] = ar;
    int mi = -1;
    if (valid){
      float at_t = atanf(tw/th);
      float best = -3.0e38f; int bi = 0;
      #pragma unroll
      for (int k = 0; k < 9; k++){
        float wb = cANW[k]*invs, hb = cANH[k]*invs;
        float ai = fminf(tw,wb)*fminf(th,hb);          // en==1 for valid boxes
        float au = tw*th + wb*hb - ai;
        float iou = ai/au;
        float mw = fmaxf(tw,wb), mh = fmaxf(th,hb);
        float c2 = mw*mw + mh*mh + 1e-16f;
        float dw = tw-wb, dh = th-hb;
        float rho2 = (dw*dw + dh*dh)*0.25f;
        float da = at_t - atanf(wb/hb);
        float v = 0.40528473455296503f*(da*da);        // 4/pi^2
        float alpha = v/(1.0f - iou + v);
        float ciou = iou - (rho2/c2 + v*alpha);
        if (ciou > best){ best = ciou; bi = k; }       // first-max, like jnp.argmax
      }
      if (bi/3 == L){
        int ii = (int)tx; ii = ii < 0 ? 0 : (ii > fs-1 ? fs-1 : ii);
        int jj = (int)ty; jj = jj < 0 ? 0 : (jj > fs-1 ? fs-1 : jj);
        mi = (bi - 3*L)*fs*fs + jj*fs + ii;
      }
    }
    g_minfo[L][b][t] = mi;
  }
}

// ---------------------------------------------------------------- prep2: ordered scatter ("last label wins") + has_match
__global__ void k_prep2(){
  int tid = threadIdx.x;
  if (tid >= 48) return;
  int L = tid >> 4, b = tid & 15;
  const int off[3] = {0, CMOFF1, CMOFF2};
  const int n3[3]  = {NC0, NC1, NC2};
  int base = off[L] + b*n3[L];
  int mi[NT];
  #pragma unroll
  for (int t = 0; t < NT; t++) mi[t] = g_minfo[L][b][t];   // batched loads (MLP)
  int hm = 0;
  #pragma unroll
  for (int t = 0; t < NT; t++){
    if (mi[t] >= 0){ hm = 1; g_cm[base + mi[t]] = t; }     // program order => last wins
  }
  g_hm[L][b] = hm;
}

// ---------------------------------------------------------------- main per-cell body
template<int L, int FS, int STRIDE, int CMOFF>
__device__ __forceinline__ void level_body(
    const float* __restrict__ x, const float* __restrict__ labels,
    int b, int chunk, int hm,
    const float4* s_box, const float* s_area, float* acc)
{
  constexpr int FSQ = FS*FS;
  int cc = chunk*256 + (int)threadIdx.x;
  if (cc >= 3*FSQ) return;
  int a = cc / FSQ;
  int cell = cc - a*FSQ;
  int i = cell % FS, j = cell / FS;
  const float* xp = x + (b*255 + a*85)*FSQ + cell;
  float o0 = __ldg(xp + 0*FSQ);
  float o1 = __ldg(xp + 1*FSQ);
  float o2 = __ldg(xp + 2*FSQ);
  float o3 = __ldg(xp + 3*FSQ);
  float o4 = __ldg(xp + 4*FSQ);
  constexpr float invs = 1.0f/STRIDE;
  float AW = cANW[3*L+a]*invs;   // exact (power-of-two divisor)
  float AH = cANH[3*L+a]*invs;
  float s0 = sigf_(o0), s1 = sigf_(o1), so = sigf_(o4);
  int m = g_cm[CMOFF + b*3*FSQ + cc];
  if (m >= 0){
    // ---- matched cell: xy / wh / obj(t=1) / cls / l2 ----
    const float* lp = labels + (b*NT+m)*5;
    float a0=__ldg(lp+0), a1=__ldg(lp+1), a2=__ldg(lp+2), a3=__ldg(lp+3), a4=__ldg(lp+4);
    float tx=(a2+a0)*(0.5f*invs), ty=(a3+a1)*(0.5f*invs);
    float tw=(a2-a0)*invs,        th=(a3-a1)*invs;
    float fx = tx - truncf(tx), fy = ty - truncf(ty);
    float lw = logf(tw/AW + 1e-16f), lh = logf(th/AH + 1e-16f);
    float scl = sqrtf(2.0f - tw*th/(float)FSQ);
    float w2 = scl*scl;
    acc[0] += w2*( -(fx*clogf_(s0) + (1.0f-fx)*clogf_(1.0f-s0))
                   -(fy*clogf_(s1) + (1.0f-fy)*clogf_(1.0f-s1)) );
    float dx = o2*scl - lw*scl;
    float dy = o3*scl - lh*scl;
    acc[1] += 0.5f*(dx*dx + dy*dy);
    acc[2] += -clogf_(so);
    float e0 = s0-fx, e1 = s1-fy, eo = so-1.0f;
    float l2 = e0*e0 + e1*e1 + dx*dx + dy*dy + eo*eo;
    int cl = (int)a4;
    float lc = 0.f;
    for (int c = 0; c < NCLS; c++){
      float scv = sigf_(__ldg(xp + (5+c)*FSQ));
      if (c == cl){ lc += -clogf_(scv);       float e = scv-1.0f; l2 += e*e; }
      else        { lc += -clogf_(1.0f-scv);  l2 += scv*scv; }
    }
    acc[3] += lc;
    acc[4] += l2;
  } else {
    // ---- unmatched cell: obj(t=0) gated by ignore mask ----
    bool keep = true;
    if (hm){
      float pw = expf(o2)*AW, ph = expf(o3)*AH;
      float px = (float)i + s0, py = (float)j + s1;
      float hw = 0.5f*pw, hh = 0.5f*ph;
      float plx = px-hw, ply = py-hh, phx = px+hw, phy = py+hh;
      float ap = pw*ph;
      bool ign = false;
      #pragma unroll 6
      for (int t = 0; t < NT; t++){
        float4 tb = s_box[t];
        float wi = fminf(phx, tb.z) - fmaxf(plx, tb.x);
        float hi = fminf(phy, tb.w) - fmaxf(ply, tb.y);
        // iou > 0.5  <=>  3*area_i > area_p + area_t   (division-free)
        ign |= (wi > 0.f) & (hi > 0.f) & (3.0f*(wi*hi) > ap + s_area[t]);
      }
      keep = !ign;
    }
    if (keep){ acc[2] += -clogf_(1.0f - so); acc[4] += so*so; }
  }
}

__global__ __launch_bounds__(256) void k_main(
    const float* __restrict__ x0, const float* __restrict__ x1, const float* __restrict__ x2,
    const float* __restrict__ labels, float* __restrict__ gout)
{
  __shared__ float4 s_box[NT];
  __shared__ float  s_area[NT];
  __shared__ float  s_red[5];
  __shared__ int    s_hm;
  int bid = blockIdx.x, tid = threadIdx.x;
  int Lv, b, chunk;
  if (bid < GB0)      { Lv = 0; b = bid/CH0;              chunk = bid - b*CH0; }
  else if (bid < GB1) { int r = bid-GB0; Lv = 1; b = r/CH1; chunk = r - b*CH1; }
  else                { int r = bid-GB1; Lv = 2; b = r/CH2; chunk = r - b*CH2; }
  if (tid < NT){ s_box[tid] = g_tbox[Lv][b][tid]; s_area[tid] = g_tarea[Lv][b][tid]; }
  if (tid == 0) s_hm = g_hm[Lv][b];
  if (tid < 5)  s_red[tid] = 0.f;
  __syncthreads();
  int hm = s_hm;
  float acc[5] = {0.f,0.f,0.f,0.f,0.f};
  if (Lv == 0)      level_body<0,76, 8, 0>     (x0, labels, b, chunk, hm, s_box, s_area, acc);
  else if (Lv == 1) level_body<1,38,16, CMOFF1>(x1, labels, b, chunk, hm, s_box, s_area, acc);
  else              level_body<2,19,32, CMOFF2>(x2, labels, b, chunk, hm, s_box, s_area, acc);
  #pragma unroll
  for (int k = 0; k < 5; k++){
    float v = acc[k];
    #pragma unroll
    for (int off = 16; off > 0; off >>= 1) v += __shfl_down_sync(0xffffffffu, v, off);
    if ((tid & 31) == 0) atomicAdd(&s_red[k], v);
  }
  __syncthreads();
  if (tid < 5) atomicAdd(&gout[1+tid], s_red[tid]);
}

__global__ void k_fin(float* __restrict__ gout){
  gout[0] = gout[1] + gout[2] + gout[3] + gout[4];
}

// ---------------------------------------------------------------- launch
extern "C" void kernel_launch(void* const* d_in, const int* in_sizes, int n_in,
                              void* d_out, int out_size)
{
  const float* x0     = (const float*)d_in[0];
  const float* x1     = (const float*)d_in[1];
  const float* x2     = (const float*)d_in[2];
  const float* labels = (const float*)d_in[3];
  float* gout = (float*)d_out;
  (void)in_sizes; (void)n_in; (void)out_size;

  k_clear<<<(NCM + 1023)/1024, 1024>>>(gout);
  k_prep1<<<(NB*NT + 255)/256, 256>>>(labels);
  k_prep2<<<1, 64>>>();
  k_main<<<GB2, 256>>>(x0, x1, x2, labels, gout);
  k_fin<<<1, 1>>>(gout);
}